// round 6
// baseline (speedup 1.0000x reference)
#include <cuda_runtime.h>
#include <cstdint>
#include <cstddef>
#include <math.h>

#define G_    8192
#define IND_  512
#define KQD_  128
#define OUTD_ 512

// ---------------- scratch (static __device__ = allowed) --------------------
__device__ float g_k[(size_t)G_ * KQD_];
__device__ float g_q[(size_t)G_ * KQD_];
__device__ float g_v[(size_t)G_ * OUTD_];
__device__ float g_vt[(size_t)OUTD_ * G_];
__device__ float g_scores[(size_t)G_ * G_];
__device__ float g_sumsq[G_];
__device__ float g_rinv[G_];

// ---------------- helpers ---------------------------------------------------
__device__ __forceinline__ uint32_t smem_u32(const void* p) {
    uint32_t a;
    asm("{ .reg .u64 t; cvta.to.shared.u64 t, %1; cvt.u32.u64 %0, t; }"
        : "=r"(a) : "l"(p));
    return a;
}
__device__ __forceinline__ float totf32(float x) {
    uint32_t o;
    asm("cvt.rna.tf32.f32 %0, %1;" : "=r"(o) : "f"(x));
    return __uint_as_float(o);
}
#define CP_ASYNC16(sm, gm) \
    asm volatile("cp.async.cg.shared.global [%0], [%1], 16;" :: "r"(sm), "l"(gm))
#define CP_COMMIT() asm volatile("cp.async.commit_group;" ::: "memory")
#define CP_WAIT(n)  asm volatile("cp.async.wait_group %0;" :: "n"(n) : "memory")

#define LDMX4(r0, r1, r2, r3, addr) \
    asm volatile("ldmatrix.sync.aligned.m8n8.x4.shared.b16 {%0,%1,%2,%3}, [%4];" \
                 : "=r"(r0), "=r"(r1), "=r"(r2), "=r"(r3) : "r"(addr))

__device__ __forceinline__ void mma_tf32(float* c, const uint32_t* a, const uint32_t* b) {
    asm volatile(
        "mma.sync.aligned.m16n8k8.row.col.f32.tf32.tf32.f32 "
        "{%0,%1,%2,%3}, {%4,%5,%6,%7}, {%8,%9}, {%0,%1,%2,%3};"
        : "+f"(c[0]), "+f"(c[1]), "+f"(c[2]), "+f"(c[3])
        : "r"(a[0]), "r"(a[1]), "r"(a[2]), "r"(a[3]), "r"(b[0]), "r"(b[1]));
}

// ===========================================================================
// Small GEMM-NT (projections, N=128): block 128x128x16, warp tile 64x32.
//   C = rna(acc + bias[col])
// ===========================================================================
__global__ void __launch_bounds__(256, 2)
proj_gemm(const float* __restrict__ A, const float* __restrict__ B,
          const float* __restrict__ bias, float* __restrict__ C,
          int K, int N)
{
    constexpr int STAGES = 4;
    constexpr int AS = 128 * 20;
    constexpr int BS = 128 * 20;

    extern __shared__ float sm[];
    const uint32_t sAu = smem_u32(sm);
    const uint32_t sBu = smem_u32(sm + STAGES * AS);

    const int tid  = threadIdx.x;
    const int warp = tid >> 5;
    const int lane = tid & 31;
    const int gr   = lane >> 2;
    const int tc   = lane & 3;
    const int wm   = (warp & 1) * 64;
    const int wn   = (warp >> 1) * 32;
    const int rowBase = blockIdx.y * 128;
    const int colBase = blockIdx.x * 128;

    const int aRow = wm + (lane & 15);
    const int aCol = (lane >> 4) << 2;
    const int bRow = wn + ((lane >> 4) << 3) + (lane & 7);
    const int bCol = ((lane >> 3) & 1) << 2;

    float acc[4][4][4];
#pragma unroll
    for (int mi = 0; mi < 4; mi++)
#pragma unroll
        for (int ni = 0; ni < 4; ni++)
#pragma unroll
            for (int r = 0; r < 4; r++) acc[mi][ni][r] = 0.f;

    const int T = K / 16;

    auto load_stage = [&](int it, int buf) {
        const int k0 = it * 16;
#pragma unroll
        for (int l = 0; l < 2; l++) {
            int c = tid + l * 256;
            int r = c >> 2, ck = (c & 3) * 4;
            CP_ASYNC16(sAu + (uint32_t)(buf * AS + r * 20 + ck) * 4,
                       A + (size_t)(rowBase + r) * K + k0 + ck);
        }
#pragma unroll
        for (int l = 0; l < 2; l++) {
            int c = tid + l * 256;
            int r = c >> 2, ck = (c & 3) * 4;
            CP_ASYNC16(sBu + (uint32_t)(buf * BS + r * 20 + ck) * 4,
                       B + (size_t)(colBase + r) * K + k0 + ck);
        }
        CP_COMMIT();
    };

#pragma unroll
    for (int s = 0; s < STAGES - 1; s++)
        if (s < T) load_stage(s, s);

    for (int i = 0; i < T; i++) {
        const int rem = T - 1 - i;
        if (rem >= 2)      { CP_WAIT(2); }
        else if (rem == 1) { CP_WAIT(1); }
        else               { CP_WAIT(0); }
        __syncthreads();
        if (i + STAGES - 1 < T) load_stage(i + STAGES - 1, (i + STAGES - 1) & (STAGES - 1));

        const uint32_t cA = sAu + (uint32_t)((i & (STAGES - 1)) * AS) * 4;
        const uint32_t cB = sBu + (uint32_t)((i & (STAGES - 1)) * BS) * 4;
#pragma unroll
        for (int ks = 0; ks < 2; ks++) {
            const int kk = ks * 8;
            uint32_t a[4][4], b[4][2];
#pragma unroll
            for (int mi = 0; mi < 4; mi++) {
                uint32_t ad = cA + (uint32_t)((aRow + mi * 16) * 20 + kk + aCol) * 4;
                LDMX4(a[mi][0], a[mi][1], a[mi][2], a[mi][3], ad);
            }
#pragma unroll
            for (int p = 0; p < 2; p++) {
                uint32_t bd = cB + (uint32_t)((bRow + p * 16) * 20 + kk + bCol) * 4;
                LDMX4(b[2 * p][0], b[2 * p][1], b[2 * p + 1][0], b[2 * p + 1][1], bd);
            }
#pragma unroll
            for (int mi = 0; mi < 4; mi++)
#pragma unroll
                for (int ni = 0; ni < 4; ni++)
                    mma_tf32(acc[mi][ni], a[mi], b[ni]);
        }
    }

#pragma unroll
    for (int mi = 0; mi < 4; mi++)
#pragma unroll
        for (int h = 0; h < 2; h++) {
            const int row = rowBase + wm + mi * 16 + h * 8 + gr;
#pragma unroll
            for (int ni = 0; ni < 4; ni++) {
                const int col = colBase + wn + ni * 8 + tc * 2;
                float2 o;
                o.x = totf32(acc[mi][ni][h * 2 + 0] + bias[col]);
                o.y = totf32(acc[mi][ni][h * 2 + 1] + bias[col + 1]);
                *reinterpret_cast<float2*>(C + (size_t)row * N + col) = o;
            }
        }
}

// ===========================================================================
// Big GEMM-NT: block 128x256x16, 8 warps, warp tile 64x64, 3-stage cp.async.
// MODE 1: C = rna(acc), sumsq[row] += row sumsq   (scores)
// MODE 2: C = rinv[row]*acc + aux[row*N+col]      (final, aux = V row-major)
// ===========================================================================
template<int MODE>
__global__ void __launch_bounds__(256, 1)
big_gemm(const float* __restrict__ A, const float* __restrict__ B,
         const float* __restrict__ aux, const float* __restrict__ rinv,
         float* __restrict__ C, float* __restrict__ sumsq,
         int K, int N)
{
    constexpr int STAGES = 3;
    constexpr int AS = 128 * 20;     // floats per A stage
    constexpr int BS = 256 * 20;     // floats per B stage

    extern __shared__ float sm[];
    const uint32_t sAu = smem_u32(sm);
    const uint32_t sBu = smem_u32(sm + STAGES * AS);

    const int tid  = threadIdx.x;
    const int warp = tid >> 5;
    const int lane = tid & 31;
    const int gr   = lane >> 2;
    const int tc   = lane & 3;
    const int wm   = (warp & 1) * 64;   // 2 warps in m
    const int wn   = (warp >> 1) * 64;  // 4 warps in n
    const int rowBase = blockIdx.y * 128;
    const int colBase = blockIdx.x * 256;

    const int aRow = wm + (lane & 15);
    const int aCol = (lane >> 4) << 2;
    const int bRow = wn + ((lane >> 4) << 3) + (lane & 7);
    const int bCol = ((lane >> 3) & 1) << 2;

    float acc[4][8][4];
#pragma unroll
    for (int mi = 0; mi < 4; mi++)
#pragma unroll
        for (int ni = 0; ni < 8; ni++)
#pragma unroll
            for (int r = 0; r < 4; r++) acc[mi][ni][r] = 0.f;

    const int T = K / 16;

    auto load_stage = [&](int it, int buf) {
        const int k0 = it * 16;
#pragma unroll
        for (int l = 0; l < 2; l++) {
            int c = tid + l * 256;
            int r = c >> 2, ck = (c & 3) * 4;
            CP_ASYNC16(sAu + (uint32_t)(buf * AS + r * 20 + ck) * 4,
                       A + (size_t)(rowBase + r) * K + k0 + ck);
        }
#pragma unroll
        for (int l = 0; l < 4; l++) {
            int c = tid + l * 256;
            int r = c >> 2, ck = (c & 3) * 4;
            CP_ASYNC16(sBu + (uint32_t)(buf * BS + r * 20 + ck) * 4,
                       B + (size_t)(colBase + r) * K + k0 + ck);
        }
        CP_COMMIT();
    };

    load_stage(0, 0);
    if (T > 1) load_stage(1, 1);

    int buf = 0;
    for (int i = 0; i < T; i++) {
        const int rem = T - 1 - i;
        if (rem >= 1) { CP_WAIT(1); }
        else          { CP_WAIT(0); }
        __syncthreads();
        if (i + 2 < T) {
            int nb = buf + 2; if (nb >= STAGES) nb -= STAGES;
            load_stage(i + 2, nb);
        }

        const uint32_t cA = sAu + (uint32_t)(buf * AS) * 4;
        const uint32_t cB = sBu + (uint32_t)(buf * BS) * 4;
#pragma unroll
        for (int ks = 0; ks < 2; ks++) {
            const int kk = ks * 8;
            uint32_t a[4][4], b[8][2];
#pragma unroll
            for (int mi = 0; mi < 4; mi++) {
                uint32_t ad = cA + (uint32_t)((aRow + mi * 16) * 20 + kk + aCol) * 4;
                LDMX4(a[mi][0], a[mi][1], a[mi][2], a[mi][3], ad);
            }
#pragma unroll
            for (int p = 0; p < 4; p++) {
                uint32_t bd = cB + (uint32_t)((bRow + p * 16) * 20 + kk + bCol) * 4;
                LDMX4(b[2 * p][0], b[2 * p][1], b[2 * p + 1][0], b[2 * p + 1][1], bd);
            }
#pragma unroll
            for (int mi = 0; mi < 4; mi++)
#pragma unroll
                for (int ni = 0; ni < 8; ni++)
                    mma_tf32(acc[mi][ni], a[mi], b[ni]);
        }
        buf++; if (buf >= STAGES) buf -= STAGES;
    }

    // ---------------- epilogue ----------------
#pragma unroll
    for (int mi = 0; mi < 4; mi++) {
#pragma unroll
        for (int h = 0; h < 2; h++) {
            const int row = rowBase + wm + mi * 16 + h * 8 + gr;
            float rv = 0.f;
            if (MODE == 2) rv = rinv[row];
            float ss = 0.f;
#pragma unroll
            for (int ni = 0; ni < 8; ni++) {
                const int col = colBase + wn + ni * 8 + tc * 2;
                float v0 = acc[mi][ni][h * 2 + 0];
                float v1 = acc[mi][ni][h * 2 + 1];
                float2 o;
                if (MODE == 1) {
                    o.x = totf32(v0);
                    o.y = totf32(v1);
                    ss += o.x * o.x + o.y * o.y;
                } else {
                    const float2 res = *reinterpret_cast<const float2*>(
                        aux + (size_t)row * N + col);
                    o.x = rv * v0 + res.x;
                    o.y = rv * v1 + res.y;
                }
                *reinterpret_cast<float2*>(C + (size_t)row * N + col) = o;
            }
            if (MODE == 1) {
                ss += __shfl_xor_sync(0xffffffffu, ss, 1);
                ss += __shfl_xor_sync(0xffffffffu, ss, 2);
                if (tc == 0) atomicAdd(&sumsq[row], ss);
            }
        }
    }
}

// ---------------------------------------------------------------------------
__global__ void transpose_k(const float* __restrict__ in, float* __restrict__ out)
{
    __shared__ float t[32][33];
    int x  = blockIdx.x * 32 + threadIdx.x;
    int y0 = blockIdx.y * 32;
#pragma unroll
    for (int i = threadIdx.y; i < 32; i += 8)
        t[i][threadIdx.x] = in[(size_t)(y0 + i) * OUTD_ + x];
    __syncthreads();
    int ox  = y0 + threadIdx.x;
    int oy0 = blockIdx.x * 32;
#pragma unroll
    for (int i = threadIdx.y; i < 32; i += 8)
        out[(size_t)(oy0 + i) * G_ + ox] = t[threadIdx.x][i];
}

__global__ void rinv_kernel(const float* __restrict__ ss, float* __restrict__ rinv)
{
    int i = blockIdx.x * 256 + threadIdx.x;
    float n = sqrtf(ss[i]);
    rinv[i] = 1.0f / fmaxf(n, 1e-12f);
}

// ---------------------------------------------------------------------------
extern "C" void kernel_launch(void* const* d_in, const int* in_sizes, int n_in,
                              void* d_out, int out_size)
{
    const float* x  = (const float*)d_in[0];
    const float* Wk = (const float*)d_in[1];
    const float* bk = (const float*)d_in[2];
    const float* Wq = (const float*)d_in[3];
    const float* bq = (const float*)d_in[4];
    const float* Wv = (const float*)d_in[5];
    const float* bv = (const float*)d_in[6];
    float* out = (float*)d_out;
    (void)in_sizes; (void)n_in; (void)out_size;

    float *pk, *pq, *pv, *pvt, *ps, *pss, *pr;
    cudaGetSymbolAddress((void**)&pk,  g_k);
    cudaGetSymbolAddress((void**)&pq,  g_q);
    cudaGetSymbolAddress((void**)&pv,  g_v);
    cudaGetSymbolAddress((void**)&pvt, g_vt);
    cudaGetSymbolAddress((void**)&ps,  g_scores);
    cudaGetSymbolAddress((void**)&pss, g_sumsq);
    cudaGetSymbolAddress((void**)&pr,  g_rinv);

    const int smemP = 4 * (128 * 20 + 128 * 20) * 4;   // 81920 B
    const int smemG = 3 * (128 * 20 + 256 * 20) * 4;   // 92160 B
    cudaFuncSetAttribute(proj_gemm,   cudaFuncAttributeMaxDynamicSharedMemorySize, smemP);
    cudaFuncSetAttribute(big_gemm<1>, cudaFuncAttributeMaxDynamicSharedMemorySize, smemG);
    cudaFuncSetAttribute(big_gemm<2>, cudaFuncAttributeMaxDynamicSharedMemorySize, smemG);

    cudaMemsetAsync(pss, 0, G_ * sizeof(float));

    // QKV projections: C = x @ W^T + b  (NT)
    proj_gemm<<<dim3(KQD_ / 128, G_ / 128), 256, smemP>>>(x, Wk, bk, pk, IND_, KQD_);
    proj_gemm<<<dim3(KQD_ / 128, G_ / 128), 256, smemP>>>(x, Wq, bq, pq, IND_, KQD_);
    proj_gemm<<<dim3(OUTD_ / 128, G_ / 128), 256, smemP>>>(x, Wv, bv, pv, IND_, OUTD_);

    // V^T so the big GEMM is NT (ldmatrix-friendly)
    transpose_k<<<dim3(OUTD_ / 32, G_ / 32), dim3(32, 8)>>>(pv, pvt);

    // scores = k @ q^T (NT), fused row sum-of-squares
    big_gemm<1><<<dim3(G_ / 256, G_ / 128), 256, smemG>>>(
        pk, pq, nullptr, nullptr, ps, pss, KQD_, G_);

    // rinv = 1 / max(||row||, eps)
    rinv_kernel<<<G_ / 256, 256>>>(pss, pr);

    // out = rinv[row] * (S @ V) + V   (NT against V^T)
    big_gemm<2><<<dim3(OUTD_ / 256, G_ / 128), 256, smemG>>>(
        ps, pvt, pv, pr, out, nullptr, G_, OUTD_);
}

// round 7
// speedup vs baseline: 2.1780x; 2.1780x over previous
#include <cuda_runtime.h>
#include <cuda_fp16.h>
#include <cstdint>
#include <cstddef>
#include <math.h>

#define G_    8192
#define IND_  512
#define KQD_  128
#define OUTD_ 512

// ---------------- scratch (static __device__ = allowed) --------------------
__device__ __half h_x[(size_t)G_ * IND_];
__device__ __half h_wk[(size_t)KQD_ * IND_];
__device__ __half h_wq[(size_t)KQD_ * IND_];
__device__ __half h_wv[(size_t)OUTD_ * IND_];
__device__ __half h_k[(size_t)G_ * KQD_];
__device__ __half h_q[(size_t)G_ * KQD_];
__device__ __half h_v[(size_t)G_ * OUTD_];
__device__ __half h_vt[(size_t)OUTD_ * G_];
__device__ __half h_s[(size_t)G_ * G_];
__device__ float  g_sumsq[G_];
__device__ float  g_rinv[G_];

// ---------------- helpers ---------------------------------------------------
__device__ __forceinline__ uint32_t smem_u32(const void* p) {
    uint32_t a;
    asm("{ .reg .u64 t; cvta.to.shared.u64 t, %1; cvt.u32.u64 %0, t; }"
        : "=r"(a) : "l"(p));
    return a;
}
#define CP_ASYNC16(sm, gm) \
    asm volatile("cp.async.cg.shared.global [%0], [%1], 16;" :: "r"(sm), "l"(gm))
#define CP_COMMIT() asm volatile("cp.async.commit_group;" ::: "memory")
#define CP_WAIT(n)  asm volatile("cp.async.wait_group %0;" :: "n"(n) : "memory")

#define LDMX4(r0, r1, r2, r3, addr) \
    asm volatile("ldmatrix.sync.aligned.m8n8.x4.shared.b16 {%0,%1,%2,%3}, [%4];" \
                 : "=r"(r0), "=r"(r1), "=r"(r2), "=r"(r3) : "r"(addr))

__device__ __forceinline__ void mma_f16(float* c, const uint32_t* a, const uint32_t* b) {
    asm volatile(
        "mma.sync.aligned.m16n8k16.row.col.f32.f16.f16.f32 "
        "{%0,%1,%2,%3}, {%4,%5,%6,%7}, {%8,%9}, {%0,%1,%2,%3};"
        : "+f"(c[0]), "+f"(c[1]), "+f"(c[2]), "+f"(c[3])
        : "r"(a[0]), "r"(a[1]), "r"(a[2]), "r"(a[3]), "r"(b[0]), "r"(b[1]));
}

// ===========================================================================
// FP16 GEMM-NT:  C[M,N] = A[M,K] @ B[N,K]^T   (A,B half, row-major)
// Block 128x128, BK=32 halves, 8 warps, warp tile 64x32, 4-stage cp.async.
// Byte layout identical to the proven tf32 kernel (stride 40 halves = 80B).
// MODE 0: Ch = h(acc + bias[col])                 (proj; aux_f = bias fp32)
// MODE 1: Ch = h(acc), sumsq[row] += row sumsq    (scores)
// MODE 2: Cf = rinv[row]*acc + float(aux_h[row,col]) (final; aux_h = V half)
// ===========================================================================
template<int MODE>
__global__ void __launch_bounds__(256, 2)
mma_gemm(const __half* __restrict__ A, const __half* __restrict__ B,
         const float* __restrict__ aux_f, const __half* __restrict__ aux_h,
         const float* __restrict__ rinv,
         __half* __restrict__ Ch, float* __restrict__ Cf,
         float* __restrict__ sumsq, int K, int N)
{
    constexpr int STAGES = 4;
    constexpr int AS = 128 * 40;   // halves per A stage (row stride 40 halves = 80B)
    constexpr int BS = 128 * 40;

    extern __shared__ __half sm[];
    const uint32_t sAu = smem_u32(sm);
    const uint32_t sBu = smem_u32(sm + STAGES * AS);

    const int tid  = threadIdx.x;
    const int warp = tid >> 5;
    const int lane = tid & 31;
    const int gr   = lane >> 2;
    const int tc   = lane & 3;
    const int wm   = (warp & 1) * 64;
    const int wn   = (warp >> 1) * 32;
    const int rowBase = blockIdx.y * 128;
    const int colBase = blockIdx.x * 128;

    // ldmatrix selects (half units)
    const int aRow  = wm + (lane & 15);
    const int aColH = (lane >> 4) << 3;                       // 0 or 8 halves
    const int bRow  = wn + ((lane >> 4) << 3) + (lane & 7);
    const int bColH = ((lane >> 3) & 1) << 3;                 // 0 or 8 halves

    float acc[4][4][4];
#pragma unroll
    for (int mi = 0; mi < 4; mi++)
#pragma unroll
        for (int ni = 0; ni < 4; ni++)
#pragma unroll
            for (int r = 0; r < 4; r++) acc[mi][ni][r] = 0.f;

    const int T = K / 32;   // 32 halves per stage

    auto load_stage = [&](int it, int buf) {
        const int k0 = it * 32;
#pragma unroll
        for (int l = 0; l < 2; l++) {
            int c = tid + l * 256;
            int r = c >> 2, ck = (c & 3) * 8;                 // 8 halves = 16B
            CP_ASYNC16(sAu + (uint32_t)(buf * AS + r * 40 + ck) * 2,
                       A + (size_t)(rowBase + r) * K + k0 + ck);
        }
#pragma unroll
        for (int l = 0; l < 2; l++) {
            int c = tid + l * 256;
            int r = c >> 2, ck = (c & 3) * 8;
            CP_ASYNC16(sBu + (uint32_t)(buf * BS + r * 40 + ck) * 2,
                       B + (size_t)(colBase + r) * K + k0 + ck);
        }
        CP_COMMIT();
    };

#pragma unroll
    for (int s = 0; s < STAGES - 1; s++)
        if (s < T) load_stage(s, s);

    for (int i = 0; i < T; i++) {
        const int rem = T - 1 - i;
        if (rem >= 2)      { CP_WAIT(2); }
        else if (rem == 1) { CP_WAIT(1); }
        else               { CP_WAIT(0); }
        __syncthreads();
        if (i + STAGES - 1 < T) load_stage(i + STAGES - 1, (i + STAGES - 1) & (STAGES - 1));

        const uint32_t cA = sAu + (uint32_t)((i & (STAGES - 1)) * AS) * 2;
        const uint32_t cB = sBu + (uint32_t)((i & (STAGES - 1)) * BS) * 2;
#pragma unroll
        for (int ks = 0; ks < 2; ks++) {
            const int kk = ks * 16;                           // halves
            uint32_t a[4][4], b[4][2];
#pragma unroll
            for (int mi = 0; mi < 4; mi++) {
                uint32_t ad = cA + (uint32_t)((aRow + mi * 16) * 40 + kk + aColH) * 2;
                LDMX4(a[mi][0], a[mi][1], a[mi][2], a[mi][3], ad);
            }
#pragma unroll
            for (int p = 0; p < 2; p++) {
                uint32_t bd = cB + (uint32_t)((bRow + p * 16) * 40 + kk + bColH) * 2;
                LDMX4(b[2 * p][0], b[2 * p][1], b[2 * p + 1][0], b[2 * p + 1][1], bd);
            }
#pragma unroll
            for (int mi = 0; mi < 4; mi++)
#pragma unroll
                for (int ni = 0; ni < 4; ni++)
                    mma_f16(acc[mi][ni], a[mi], b[ni]);
        }
    }

    // ---------------- epilogue ----------------
#pragma unroll
    for (int mi = 0; mi < 4; mi++) {
#pragma unroll
        for (int h = 0; h < 2; h++) {
            const int row = rowBase + wm + mi * 16 + h * 8 + gr;
            float rv = 0.f;
            if (MODE == 2) rv = rinv[row];
            float ss = 0.f;
#pragma unroll
            for (int ni = 0; ni < 4; ni++) {
                const int col = colBase + wn + ni * 8 + tc * 2;
                float v0 = acc[mi][ni][h * 2 + 0];
                float v1 = acc[mi][ni][h * 2 + 1];
                if (MODE == 0) {
                    __half2 o = __floats2half2_rn(v0 + aux_f[col], v1 + aux_f[col + 1]);
                    *reinterpret_cast<__half2*>(Ch + (size_t)row * N + col) = o;
                } else if (MODE == 1) {
                    __half2 o = __floats2half2_rn(v0, v1);
                    float2 of = __half22float2(o);
                    ss += of.x * of.x + of.y * of.y;
                    *reinterpret_cast<__half2*>(Ch + (size_t)row * N + col) = o;
                } else {
                    float2 res = __half22float2(
                        *reinterpret_cast<const __half2*>(aux_h + (size_t)row * N + col));
                    float2 o;
                    o.x = rv * v0 + res.x;
                    o.y = rv * v1 + res.y;
                    *reinterpret_cast<float2*>(Cf + (size_t)row * N + col) = o;
                }
            }
            if (MODE == 1) {
                ss += __shfl_xor_sync(0xffffffffu, ss, 1);
                ss += __shfl_xor_sync(0xffffffffu, ss, 2);
                if (tc == 0) atomicAdd(&sumsq[row], ss);
            }
        }
    }
}

// ---------------------------------------------------------------------------
__global__ void f2h(const float* __restrict__ in, __half* __restrict__ out, int n2)
{
    int i = blockIdx.x * 256 + threadIdx.x;
    if (i < n2) {
        float2 v = reinterpret_cast<const float2*>(in)[i];
        reinterpret_cast<__half2*>(out)[i] = __floats2half2_rn(v.x, v.y);
    }
}

__global__ void transpose_h(const __half* __restrict__ in, __half* __restrict__ out)
{
    __shared__ __half t[32][33];
    int x  = blockIdx.x * 32 + threadIdx.x;   // col of in (0..OUTD-1)
    int y0 = blockIdx.y * 32;                 // row of in
#pragma unroll
    for (int i = threadIdx.y; i < 32; i += 8)
        t[i][threadIdx.x] = in[(size_t)(y0 + i) * OUTD_ + x];
    __syncthreads();
    int ox  = y0 + threadIdx.x;
    int oy0 = blockIdx.x * 32;
#pragma unroll
    for (int i = threadIdx.y; i < 32; i += 8)
        out[(size_t)(oy0 + i) * G_ + ox] = t[threadIdx.x][i];
}

__global__ void rinv_kernel(const float* __restrict__ ss, float* __restrict__ rinv)
{
    int i = blockIdx.x * 256 + threadIdx.x;
    float n = sqrtf(ss[i]);
    rinv[i] = 1.0f / fmaxf(n, 1e-12f);
}

// ---------------------------------------------------------------------------
extern "C" void kernel_launch(void* const* d_in, const int* in_sizes, int n_in,
                              void* d_out, int out_size)
{
    const float* x  = (const float*)d_in[0];
    const float* Wk = (const float*)d_in[1];
    const float* bk = (const float*)d_in[2];
    const float* Wq = (const float*)d_in[3];
    const float* bq = (const float*)d_in[4];
    const float* Wv = (const float*)d_in[5];
    const float* bv = (const float*)d_in[6];
    float* out = (float*)d_out;
    (void)in_sizes; (void)n_in; (void)out_size;

    __half *px, *pwk, *pwq, *pwv, *pk, *pq, *pv, *pvt, *ps;
    float *pss, *pr;
    cudaGetSymbolAddress((void**)&px,  h_x);
    cudaGetSymbolAddress((void**)&pwk, h_wk);
    cudaGetSymbolAddress((void**)&pwq, h_wq);
    cudaGetSymbolAddress((void**)&pwv, h_wv);
    cudaGetSymbolAddress((void**)&pk,  h_k);
    cudaGetSymbolAddress((void**)&pq,  h_q);
    cudaGetSymbolAddress((void**)&pv,  h_v);
    cudaGetSymbolAddress((void**)&pvt, h_vt);
    cudaGetSymbolAddress((void**)&ps,  h_s);
    cudaGetSymbolAddress((void**)&pss, g_sumsq);
    cudaGetSymbolAddress((void**)&pr,  g_rinv);

    const int smemB = 4 * (128 * 40 + 128 * 40) * 2;   // 81920 B
    cudaFuncSetAttribute(mma_gemm<0>, cudaFuncAttributeMaxDynamicSharedMemorySize, smemB);
    cudaFuncSetAttribute(mma_gemm<1>, cudaFuncAttributeMaxDynamicSharedMemorySize, smemB);
    cudaFuncSetAttribute(mma_gemm<2>, cudaFuncAttributeMaxDynamicSharedMemorySize, smemB);

    cudaMemsetAsync(pss, 0, G_ * sizeof(float));

    // fp32 -> fp16 copies (so cp.async streams half data directly)
    f2h<<<(G_ * IND_ / 2 + 255) / 256, 256>>>(x,  px,  G_ * IND_ / 2);
    f2h<<<(KQD_ * IND_ / 2 + 255) / 256, 256>>>(Wk, pwk, KQD_ * IND_ / 2);
    f2h<<<(KQD_ * IND_ / 2 + 255) / 256, 256>>>(Wq, pwq, KQD_ * IND_ / 2);
    f2h<<<(OUTD_ * IND_ / 2 + 255) / 256, 256>>>(Wv, pwv, OUTD_ * IND_ / 2);

    // QKV projections: C = x @ W^T + b  (NT, half out)
    mma_gemm<0><<<dim3(KQD_ / 128, G_ / 128), 256, smemB>>>(
        px, pwk, bk, nullptr, nullptr, pk, nullptr, nullptr, IND_, KQD_);
    mma_gemm<0><<<dim3(KQD_ / 128, G_ / 128), 256, smemB>>>(
        px, pwq, bq, nullptr, nullptr, pq, nullptr, nullptr, IND_, KQD_);
    mma_gemm<0><<<dim3(OUTD_ / 128, G_ / 128), 256, smemB>>>(
        px, pwv, bv, nullptr, nullptr, pv, nullptr, nullptr, IND_, OUTD_);

    // V^T (half) for the NT big GEMM
    transpose_h<<<dim3(OUTD_ / 32, G_ / 32), dim3(32, 8)>>>(pv, pvt);

    // scores = k @ q^T (NT), fused row sum-of-squares
    mma_gemm<1><<<dim3(G_ / 128, G_ / 128), 256, smemB>>>(
        pk, pq, nullptr, nullptr, nullptr, ps, nullptr, pss, KQD_, G_);

    // rinv = 1 / max(||row||, eps)
    rinv_kernel<<<G_ / 256, 256>>>(pss, pr);

    // out = rinv[row] * (S @ V) + V   (NT against V^T, fp32 out)
    mma_gemm<2><<<dim3(OUTD_ / 128, G_ / 128), 256, smemB>>>(
        ps, pvt, nullptr, pv, pr, nullptr, out, nullptr, G_, OUTD_);
}

// round 8
// speedup vs baseline: 2.4615x; 1.1302x over previous
#include <cuda_runtime.h>
#include <cuda_fp16.h>
#include <cstdint>
#include <cstddef>
#include <math.h>

#define G_    8192
#define IND_  512
#define KQD_  128
#define OUTD_ 512
#define NP_   768     // packed k|q|v columns

// ---------------- scratch (static __device__ = allowed) --------------------
__device__ __half h_x[(size_t)G_ * IND_];
__device__ __half h_w[(size_t)NP_ * IND_];     // packed [Wk;Wq;Wv]
__device__ float  g_bias[NP_];                 // packed [bk;bq;bv]
__device__ __half h_kqv[(size_t)G_ * NP_];     // packed [k|q|v]
__device__ __half h_vt[(size_t)OUTD_ * G_];
__device__ __half h_s[(size_t)G_ * G_];
__device__ float  g_sumsq[G_];
__device__ float  g_rinv[G_];

// ---------------- helpers ---------------------------------------------------
__device__ __forceinline__ uint32_t smem_u32(const void* p) {
    uint32_t a;
    asm("{ .reg .u64 t; cvta.to.shared.u64 t, %1; cvt.u32.u64 %0, t; }"
        : "=r"(a) : "l"(p));
    return a;
}
#define CP_ASYNC16(sm, gm) \
    asm volatile("cp.async.cg.shared.global [%0], [%1], 16;" :: "r"(sm), "l"(gm))
#define CP_COMMIT() asm volatile("cp.async.commit_group;" ::: "memory")
#define CP_WAIT(n)  asm volatile("cp.async.wait_group %0;" :: "n"(n) : "memory")

#define LDMX4(r0, r1, r2, r3, addr) \
    asm volatile("ldmatrix.sync.aligned.m8n8.x4.shared.b16 {%0,%1,%2,%3}, [%4];" \
                 : "=r"(r0), "=r"(r1), "=r"(r2), "=r"(r3) : "r"(addr))

__device__ __forceinline__ void mma_f16(float* c, const uint32_t* a, const uint32_t* b) {
    asm volatile(
        "mma.sync.aligned.m16n8k16.row.col.f32.f16.f16.f32 "
        "{%0,%1,%2,%3}, {%4,%5,%6,%7}, {%8,%9}, {%0,%1,%2,%3};"
        : "+f"(c[0]), "+f"(c[1]), "+f"(c[2]), "+f"(c[3])
        : "r"(a[0]), "r"(a[1]), "r"(a[2]), "r"(a[3]), "r"(b[0]), "r"(b[1]));
}

// ===========================================================================
// FP16 GEMM-NT:  C[M,N] = A[M,K] @ B[N,K]^T   (half, row-major, strided lds)
// Block 128x128, BK=32 halves, 4 warps (128 thr), warp tile 64x64,
// 4-stage cp.async, 2 CTA/SM.
// MODE 0: Ch = h(acc + bias[col])                 (proj; aux_f = bias fp32)
// MODE 1: Ch = h(acc), sumsq[row] += row sumsq    (scores)
// MODE 2: Cf = rinv[row]*acc + float(aux_h[row*ldaux+col]) (final)
// ===========================================================================
template<int MODE>
__global__ void __launch_bounds__(128, 2)
mma_gemm(const __half* __restrict__ A, const __half* __restrict__ B,
         const float* __restrict__ aux_f, const __half* __restrict__ aux_h,
         const float* __restrict__ rinv,
         __half* __restrict__ Ch, float* __restrict__ Cf,
         float* __restrict__ sumsq,
         int K, int lda, int ldb, int ldc, int ldaux)
{
    constexpr int STAGES = 4;
    constexpr int AS = 128 * 40;   // halves per A stage (row stride 40 halves = 80B)
    constexpr int BS = 128 * 40;

    extern __shared__ __half sm[];
    const uint32_t sAu = smem_u32(sm);
    const uint32_t sBu = smem_u32(sm + STAGES * AS);

    const int tid  = threadIdx.x;
    const int warp = tid >> 5;
    const int lane = tid & 31;
    const int gr   = lane >> 2;
    const int tc   = lane & 3;
    const int wm   = (warp & 1) * 64;
    const int wn   = (warp >> 1) * 64;
    const int rowBase = blockIdx.y * 128;
    const int colBase = blockIdx.x * 128;

    // ldmatrix selects (half units)
    const int aRow  = wm + (lane & 15);
    const int aColH = (lane >> 4) << 3;                       // 0 or 8 halves
    const int bRow  = wn + ((lane >> 4) << 3) + (lane & 7);
    const int bColH = ((lane >> 3) & 1) << 3;                 // 0 or 8 halves

    float acc[4][8][4];
#pragma unroll
    for (int mi = 0; mi < 4; mi++)
#pragma unroll
        for (int ni = 0; ni < 8; ni++)
#pragma unroll
            for (int r = 0; r < 4; r++) acc[mi][ni][r] = 0.f;

    const int T = K / 32;   // 32 halves per stage

    auto load_stage = [&](int it, int buf) {
        const int k0 = it * 32;
#pragma unroll
        for (int l = 0; l < 4; l++) {
            int c = tid + l * 128;
            int r = c >> 2, ck = (c & 3) * 8;                 // 8 halves = 16B
            CP_ASYNC16(sAu + (uint32_t)(buf * AS + r * 40 + ck) * 2,
                       A + (size_t)(rowBase + r) * lda + k0 + ck);
        }
#pragma unroll
        for (int l = 0; l < 4; l++) {
            int c = tid + l * 128;
            int r = c >> 2, ck = (c & 3) * 8;
            CP_ASYNC16(sBu + (uint32_t)(buf * BS + r * 40 + ck) * 2,
                       B + (size_t)(colBase + r) * ldb + k0 + ck);
        }
        CP_COMMIT();
    };

#pragma unroll
    for (int s = 0; s < STAGES - 1; s++)
        if (s < T) load_stage(s, s);

    for (int i = 0; i < T; i++) {
        const int rem = T - 1 - i;
        if (rem >= 2)      { CP_WAIT(2); }
        else if (rem == 1) { CP_WAIT(1); }
        else               { CP_WAIT(0); }
        __syncthreads();
        if (i + STAGES - 1 < T) load_stage(i + STAGES - 1, (i + STAGES - 1) & (STAGES - 1));

        const uint32_t cA = sAu + (uint32_t)((i & (STAGES - 1)) * AS) * 2;
        const uint32_t cB = sBu + (uint32_t)((i & (STAGES - 1)) * BS) * 2;
#pragma unroll
        for (int ks = 0; ks < 2; ks++) {
            const int kk = ks * 16;                           // halves
            uint32_t a[4][4], b[8][2];
#pragma unroll
            for (int mi = 0; mi < 4; mi++) {
                uint32_t ad = cA + (uint32_t)((aRow + mi * 16) * 40 + kk + aColH) * 2;
                LDMX4(a[mi][0], a[mi][1], a[mi][2], a[mi][3], ad);
            }
#pragma unroll
            for (int p = 0; p < 4; p++) {
                uint32_t bd = cB + (uint32_t)((bRow + p * 16) * 40 + kk + bColH) * 2;
                LDMX4(b[2 * p][0], b[2 * p][1], b[2 * p + 1][0], b[2 * p + 1][1], bd);
            }
#pragma unroll
            for (int mi = 0; mi < 4; mi++)
#pragma unroll
                for (int ni = 0; ni < 8; ni++)
                    mma_f16(acc[mi][ni], a[mi], b[ni]);
        }
    }

    // ---------------- epilogue ----------------
#pragma unroll
    for (int mi = 0; mi < 4; mi++) {
#pragma unroll
        for (int h = 0; h < 2; h++) {
            const int row = rowBase + wm + mi * 16 + h * 8 + gr;
            float rv = 0.f;
            if (MODE == 2) rv = rinv[row];
            float ss = 0.f;
#pragma unroll
            for (int ni = 0; ni < 8; ni++) {
                const int col = colBase + wn + ni * 8 + tc * 2;
                float v0 = acc[mi][ni][h * 2 + 0];
                float v1 = acc[mi][ni][h * 2 + 1];
                if (MODE == 0) {
                    __half2 o = __floats2half2_rn(v0 + aux_f[col], v1 + aux_f[col + 1]);
                    *reinterpret_cast<__half2*>(Ch + (size_t)row * ldc + col) = o;
                } else if (MODE == 1) {
                    __half2 o = __floats2half2_rn(v0, v1);
                    float2 of = __half22float2(o);
                    ss += of.x * of.x + of.y * of.y;
                    *reinterpret_cast<__half2*>(Ch + (size_t)row * ldc + col) = o;
                } else {
                    float2 res = __half22float2(
                        *reinterpret_cast<const __half2*>(aux_h + (size_t)row * ldaux + col));
                    float2 o;
                    o.x = rv * v0 + res.x;
                    o.y = rv * v1 + res.y;
                    *reinterpret_cast<float2*>(Cf + (size_t)row * ldc + col) = o;
                }
            }
            if (MODE == 1) {
                ss += __shfl_xor_sync(0xffffffffu, ss, 1);
                ss += __shfl_xor_sync(0xffffffffu, ss, 2);
                if (tc == 0) atomicAdd(&sumsq[row], ss);
            }
        }
    }
}

// ---------------------------------------------------------------------------
__global__ void f2h(const float* __restrict__ in, __half* __restrict__ out, int n2)
{
    int i = blockIdx.x * 256 + threadIdx.x;
    if (i < n2) {
        float2 v = reinterpret_cast<const float2*>(in)[i];
        reinterpret_cast<__half2*>(out)[i] = __floats2half2_rn(v.x, v.y);
    }
}

// pack [Wk;Wq;Wv] -> h_w [768x512] fp16
__global__ void pack_w(const float* __restrict__ wk, const float* __restrict__ wq,
                       const float* __restrict__ wv, __half* __restrict__ out)
{
    int i = blockIdx.x * 256 + threadIdx.x;        // over 768*512/2
    if (i >= NP_ * IND_ / 2) return;
    int row = i / (IND_ / 2);
    int c2  = i % (IND_ / 2);
    const float* src; int sr;
    if (row < KQD_)          { src = wk; sr = row; }
    else if (row < 2 * KQD_) { src = wq; sr = row - KQD_; }
    else                     { src = wv; sr = row - 2 * KQD_; }
    float2 v = reinterpret_cast<const float2*>(src + (size_t)sr * IND_)[c2];
    reinterpret_cast<__half2*>(out + (size_t)row * IND_)[c2] = __floats2half2_rn(v.x, v.y);
}

__global__ void pack_bias(const float* __restrict__ bk, const float* __restrict__ bq,
                          const float* __restrict__ bv, float* __restrict__ out)
{
    int i = threadIdx.x;   // 768 threads
    if (i < KQD_)          out[i] = bk[i];
    else if (i < 2 * KQD_) out[i] = bq[i - KQD_];
    else                   out[i] = bv[i - 2 * KQD_];
}

// transpose V (strided source inside packed kqv) -> h_vt [512 x 8192]
__global__ void transpose_h(const __half* __restrict__ in, int ldin,
                            __half* __restrict__ out)
{
    __shared__ __half t[32][33];
    int x  = blockIdx.x * 32 + threadIdx.x;   // col of V (0..511)
    int y0 = blockIdx.y * 32;                 // row of V
#pragma unroll
    for (int i = threadIdx.y; i < 32; i += 8)
        t[i][threadIdx.x] = in[(size_t)(y0 + i) * ldin + x];
    __syncthreads();
    int ox  = y0 + threadIdx.x;
    int oy0 = blockIdx.x * 32;
#pragma unroll
    for (int i = threadIdx.y; i < 32; i += 8)
        out[(size_t)(oy0 + i) * G_ + ox] = t[threadIdx.x][i];
}

__global__ void rinv_kernel(const float* __restrict__ ss, float* __restrict__ rinv)
{
    int i = blockIdx.x * 256 + threadIdx.x;
    float n = sqrtf(ss[i]);
    rinv[i] = 1.0f / fmaxf(n, 1e-12f);
}

// ---------------------------------------------------------------------------
extern "C" void kernel_launch(void* const* d_in, const int* in_sizes, int n_in,
                              void* d_out, int out_size)
{
    const float* x  = (const float*)d_in[0];
    const float* Wk = (const float*)d_in[1];
    const float* bk = (const float*)d_in[2];
    const float* Wq = (const float*)d_in[3];
    const float* bq = (const float*)d_in[4];
    const float* Wv = (const float*)d_in[5];
    const float* bv = (const float*)d_in[6];
    float* out = (float*)d_out;
    (void)in_sizes; (void)n_in; (void)out_size;

    __half *px, *pw, *pkqv, *pvt, *ps;
    float *pb, *pss, *pr;
    cudaGetSymbolAddress((void**)&px,   h_x);
    cudaGetSymbolAddress((void**)&pw,   h_w);
    cudaGetSymbolAddress((void**)&pb,   g_bias);
    cudaGetSymbolAddress((void**)&pkqv, h_kqv);
    cudaGetSymbolAddress((void**)&pvt,  h_vt);
    cudaGetSymbolAddress((void**)&ps,   h_s);
    cudaGetSymbolAddress((void**)&pss,  g_sumsq);
    cudaGetSymbolAddress((void**)&pr,   g_rinv);

    const int smemB = 4 * (128 * 40 + 128 * 40) * 2;   // 81920 B
    cudaFuncSetAttribute(mma_gemm<0>, cudaFuncAttributeMaxDynamicSharedMemorySize, smemB);
    cudaFuncSetAttribute(mma_gemm<1>, cudaFuncAttributeMaxDynamicSharedMemorySize, smemB);
    cudaFuncSetAttribute(mma_gemm<2>, cudaFuncAttributeMaxDynamicSharedMemorySize, smemB);

    cudaMemsetAsync(pss, 0, G_ * sizeof(float));

    // fp32 -> fp16 conversions / packing
    f2h<<<(G_ * IND_ / 2 + 255) / 256, 256>>>(x, px, G_ * IND_ / 2);
    pack_w<<<(NP_ * IND_ / 2 + 255) / 256, 256>>>(Wk, Wq, Wv, pw);
    pack_bias<<<1, NP_>>>(bk, bq, bv, pb);

    // fused QKV projection: kqv = x @ [Wk;Wq;Wv]^T + [bk;bq;bv]
    mma_gemm<0><<<dim3(NP_ / 128, G_ / 128), 128, smemB>>>(
        px, pw, pb, nullptr, nullptr, pkqv, nullptr, nullptr,
        IND_, IND_, IND_, NP_, 0);

    // V^T for the NT big GEMM (V = kqv cols [256..768))
    transpose_h<<<dim3(OUTD_ / 32, G_ / 32), dim3(32, 8)>>>(pkqv + 2 * KQD_, NP_, pvt);

    // scores = k @ q^T (NT), fused row sum-of-squares
    mma_gemm<1><<<dim3(G_ / 128, G_ / 128), 128, smemB>>>(
        pkqv, pkqv + KQD_, nullptr, nullptr, nullptr, ps, nullptr, pss,
        KQD_, NP_, NP_, G_, 0);

    // rinv = 1 / max(||row||, eps)
    rinv_kernel<<<G_ / 256, 256>>>(pss, pr);

    // out = rinv[row] * (S @ V) + V   (NT against V^T, fp32 out)
    mma_gemm<2><<<dim3(OUTD_ / 128, G_ / 128), 128, smemB>>>(
        ps, pvt, nullptr, pkqv + 2 * KQD_, pr, nullptr, out, nullptr,
        G_, G_, G_, OUTD_, NP_);
}